// round 2
// baseline (speedup 1.0000x reference)
#include <cuda_runtime.h>
#include <cuda_bf16.h>
#include <math.h>

// Problem constants
#define TB 2
#define TT 2048
#define TD 1024
#define NQH 16
#define NKH 8
#define HD 128
#define BT (TB*TT)          // 4096 rows
#define QKV_LD 4096         // q(2048) | k(1024) | v(1024)
#define EPSV 1e-6f
#define SCALEV 0.08838834764831845f   // 128^-0.5
#define KMASK (-3.40282346638528860e+38f)
#define LOG2_THETA 19.9315685693241740f // log2(1e6)

// Scratch (device globals; no runtime allocation)
__device__ float g_qkv[(size_t)BT * QKV_LD];   // 64MB
__device__ float g_att[(size_t)BT * (NQH*HD)]; // 32MB
__device__ int   g_pos[BT];

// ---------------------------------------------------------------------------
// Kernel 1: positions from segment ids (per-batch argmax-of-max offset)
// ---------------------------------------------------------------------------
__global__ void pos_kernel(const int* __restrict__ seg, int* __restrict__ pos) {
    const int b = blockIdx.x;
    const int tid = threadIdx.x;
    __shared__ int red[256];
    int mx = -2147483647 - 1;
    for (int t = tid; t < TT; t += 256) mx = max(mx, seg[b*TT + t]);
    red[tid] = mx; __syncthreads();
    for (int s = 128; s > 0; s >>= 1) {
        if (tid < s) red[tid] = max(red[tid], red[tid + s]);
        __syncthreads();
    }
    const int gmax = red[0];
    __syncthreads();
    int idx = TT;
    for (int t = tid; t < TT; t += 256)
        if (seg[b*TT + t] == gmax && t < idx) idx = t;
    red[tid] = idx; __syncthreads();
    for (int s = 128; s > 0; s >>= 1) {
        if (tid < s) red[tid] = min(red[tid], red[tid + s]);
        __syncthreads();
    }
    const int off = red[0];
    for (int t = tid; t < TT; t += 256) {
        int sv = seg[b*TT + t];
        pos[b*TT + t] = (sv != 0) ? (t - off) : (1 << 30);
    }
}

// ---------------------------------------------------------------------------
// Kernel 2: generic SGEMM  C[M,N] = A[M,Kd] @ B[Kd,N]
// 128x64 block tile, 16 k-step, 256 threads, 8x4 per-thread tile
// ---------------------------------------------------------------------------
#define GBM 128
#define GBN 64
#define GBK 16

__global__ __launch_bounds__(256) void sgemm_kernel(
    const float* __restrict__ A, int lda,
    const float* __restrict__ B, int ldb,
    float* __restrict__ C, int ldc,
    int M, int N, int Kd)
{
    __shared__ float As[GBK][GBM + 4];   // transposed: As[k][m]
    __shared__ float Bs[GBK][GBN + 4];

    const int tid = threadIdx.x;
    const int tx = tid & 15;
    const int ty = tid >> 4;
    const int m0 = blockIdx.y * GBM;
    const int n0 = blockIdx.x * GBN;
    const int row_m = ty * 8;
    const int col_n = tx * 4;

    float acc[8][4];
#pragma unroll
    for (int i = 0; i < 8; i++)
#pragma unroll
        for (int j = 0; j < 4; j++) acc[i][j] = 0.f;

    for (int k0 = 0; k0 < Kd; k0 += GBK) {
        // A tile: 128x16 = 512 float4 loads, 2 per thread, write transposed
#pragma unroll
        for (int i = 0; i < 2; i++) {
            int f = tid + i * 256;
            int r = f >> 2;            // row 0..127
            int kc = (f & 3) * 4;      // 0,4,8,12
            float4 v = *(const float4*)&A[(size_t)(m0 + r) * lda + k0 + kc];
            As[kc + 0][r] = v.x;
            As[kc + 1][r] = v.y;
            As[kc + 2][r] = v.z;
            As[kc + 3][r] = v.w;
        }
        // B tile: 16x64 = 256 float4 loads, 1 per thread
        {
            int r = tid >> 4;          // k 0..15
            int c = (tid & 15) * 4;
            float4 v = *(const float4*)&B[(size_t)(k0 + r) * ldb + n0 + c];
            *(float4*)&Bs[r][c] = v;
        }
        __syncthreads();
#pragma unroll
        for (int kk = 0; kk < GBK; kk++) {
            float4 a0 = *(const float4*)&As[kk][row_m];
            float4 a1 = *(const float4*)&As[kk][row_m + 4];
            float4 b  = *(const float4*)&Bs[kk][col_n];
            float av[8] = {a0.x, a0.y, a0.z, a0.w, a1.x, a1.y, a1.z, a1.w};
            float bv[4] = {b.x, b.y, b.z, b.w};
#pragma unroll
            for (int i = 0; i < 8; i++)
#pragma unroll
                for (int j = 0; j < 4; j++)
                    acc[i][j] += av[i] * bv[j];
        }
        __syncthreads();
    }
#pragma unroll
    for (int i = 0; i < 8; i++) {
        int m = m0 + row_m + i;
        float4 v = make_float4(acc[i][0], acc[i][1], acc[i][2], acc[i][3]);
        *(float4*)&C[(size_t)m * ldc + n0 + col_n] = v;
    }
}

// ---------------------------------------------------------------------------
// Kernel 3: in-place RMSNorm + RoPE on q and k columns of g_qkv
// grid (BT, NQH+NKH), 128 threads (one per h)
// ---------------------------------------------------------------------------
__global__ void normrope_kernel(float* __restrict__ qkv,
                                const int* __restrict__ pos,
                                const float* __restrict__ q_scale,
                                const float* __restrict__ k_scale)
{
    const int bt = blockIdx.x;
    const int head = blockIdx.y;      // 0..15 q, 16..23 k
    const int h = threadIdx.x;        // 0..127
    const bool isq = head < NQH;
    const int colbase = isq ? head * HD : (NQH*HD) + (head - NQH) * HD;
    float* base = qkv + (size_t)bt * QKV_LD + colbase;

    float v = base[h];
    float ss = v * v;
#pragma unroll
    for (int d = 16; d > 0; d >>= 1) ss += __shfl_xor_sync(0xFFFFFFFFu, ss, d);
    __shared__ float wsum[4];
    const int lane = h & 31, wid = h >> 5;
    if (lane == 0) wsum[wid] = ss;
    __syncthreads();
    float total = wsum[0] + wsum[1] + wsum[2] + wsum[3];
    float rms = sqrtf(total * (1.0f / HD) + EPSV);
    const float* sc = isq ? q_scale : k_scale;
    float nv = sc[h] * v / rms;

    __shared__ float buf[HD];
    buf[h] = nv;
    __syncthreads();

    const int p = pos[bt];
    if (h < HD/2) {
        float x1 = buf[h];
        float x2 = buf[h + HD/2];
        float inv_freq = exp2f(-(float)h * (LOG2_THETA / (HD/2)));
        float ang = (float)p * inv_freq;
        float s, c;
        sincosf(ang, &s, &c);
        base[h]        = x1 * c - x2 * s;
        base[h + HD/2] = x2 * c + x1 * s;
    }
}

// ---------------------------------------------------------------------------
// Kernel 4: flash attention (fp32, online softmax)
// grid (T/64, NQH, B), 256 threads; Bq=Bk=64
// ---------------------------------------------------------------------------
#define FQ 64
#define FK 64
// smem floats: Qs 128*68 + KsPs 128*68 + Vs 64*132 = 25856 floats
#define FLASH_SMEM_BYTES (25856 * 4 + 4 * 64 * 4)

__global__ __launch_bounds__(256) void flash_kernel(
    const float* __restrict__ qkv, const int* __restrict__ pos,
    const int* __restrict__ seg, float* __restrict__ att)
{
    extern __shared__ float sm[];
    float* Qs   = sm;                   // [128][68] transposed, pre-scaled
    float* KsPs = Qs + 128 * 68;        // Ks [128][68] transposed / Ps [64][68]
    float* Vs   = KsPs + 128 * 68;      // [64][132]
    int* posq = (int*)(Vs + 64 * 132);  // [64]
    int* segq = posq + 64;
    int* posk = segq + 64;
    int* segk = posk + 64;

    const int tid = threadIdx.x;
    const int tx = tid & 15;
    const int ty = tid >> 4;
    const int qt = blockIdx.x;
    const int n  = blockIdx.y;
    const int b  = blockIdx.z;
    const int kh = n >> 1;              // n / G, G=2
    const int q0 = qt * FQ;

    const float* qbase = qkv + (size_t)(b*TT + q0) * QKV_LD + n * HD;

    // Load Q tile transposed + pre-scaled
#pragma unroll
    for (int i = 0; i < 8; i++) {
        int f = tid + i * 256;          // 0..2047
        int m = f >> 5;                 // 0..63
        int kc = (f & 31) * 4;          // 0..124
        float4 v = *(const float4*)&qbase[(size_t)m * QKV_LD + kc];
        Qs[(kc + 0) * 68 + m] = v.x * SCALEV;
        Qs[(kc + 1) * 68 + m] = v.y * SCALEV;
        Qs[(kc + 2) * 68 + m] = v.z * SCALEV;
        Qs[(kc + 3) * 68 + m] = v.w * SCALEV;
    }
    if (tid < FQ) {
        posq[tid] = pos[b*TT + q0 + tid];
        segq[tid] = seg[b*TT + q0 + tid];
    }
    __syncthreads();

    float m_run[4], l_run[4];
#pragma unroll
    for (int i = 0; i < 4; i++) { m_run[i] = -1e30f; l_run[i] = 0.f; }
    float acc[4][8];
#pragma unroll
    for (int i = 0; i < 4; i++)
#pragma unroll
        for (int j = 0; j < 8; j++) acc[i][j] = 0.f;

    const int ntiles = qt + 1;          // causal: pos == t for this input
    for (int kt = 0; kt < ntiles; kt++) {
        const int s0 = kt * FK;
        const float* kbase = qkv + (size_t)(b*TT + s0) * QKV_LD + (NQH*HD) + kh * HD;
        const float* vbase = qkv + (size_t)(b*TT + s0) * QKV_LD + (NQH*HD + NKH*HD) + kh * HD;
#pragma unroll
        for (int i = 0; i < 8; i++) {
            int f = tid + i * 256;
            int s = f >> 5;
            int kc = (f & 31) * 4;
            float4 v = *(const float4*)&kbase[(size_t)s * QKV_LD + kc];
            KsPs[(kc + 0) * 68 + s] = v.x;
            KsPs[(kc + 1) * 68 + s] = v.y;
            KsPs[(kc + 2) * 68 + s] = v.z;
            KsPs[(kc + 3) * 68 + s] = v.w;
            float4 w = *(const float4*)&vbase[(size_t)s * QKV_LD + kc];
            *(float4*)&Vs[s * 132 + kc] = w;
        }
        if (tid < FK) {
            posk[tid] = pos[b*TT + s0 + tid];
            segk[tid] = seg[b*TT + s0 + tid];
        }
        __syncthreads();

        // ---- S = Q K^T (scaled) ----
        float sv[4][4];
#pragma unroll
        for (int i = 0; i < 4; i++)
#pragma unroll
            for (int j = 0; j < 4; j++) sv[i][j] = 0.f;
#pragma unroll 8
        for (int kk = 0; kk < HD; kk++) {
            float4 qa = *(const float4*)&Qs[kk * 68 + ty * 4];
            float4 ka = *(const float4*)&KsPs[kk * 68 + tx * 4];
            float qv[4] = {qa.x, qa.y, qa.z, qa.w};
            float kv[4] = {ka.x, ka.y, ka.z, ka.w};
#pragma unroll
            for (int i = 0; i < 4; i++)
#pragma unroll
                for (int j = 0; j < 4; j++)
                    sv[i][j] += qv[i] * kv[j];
        }

        // ---- mask ----
        int pq[4], sq[4], pk[4], sk[4];
#pragma unroll
        for (int i = 0; i < 4; i++) { pq[i] = posq[ty*4 + i]; sq[i] = segq[ty*4 + i]; }
#pragma unroll
        for (int j = 0; j < 4; j++) { pk[j] = posk[tx*4 + j]; sk[j] = segk[tx*4 + j]; }
#pragma unroll
        for (int i = 0; i < 4; i++)
#pragma unroll
            for (int j = 0; j < 4; j++) {
                bool valid = (pk[j] <= pq[i]) && (sk[j] == sq[i]);
                sv[i][j] = valid ? sv[i][j] : KMASK;
            }

        // ---- online softmax stats (per-row, across the 16 tx lanes) ----
        float tmax[4], nm[4], alpha[4], rs[4];
#pragma unroll
        for (int i = 0; i < 4; i++) {
            float t = sv[i][0];
            t = fmaxf(t, sv[i][1]); t = fmaxf(t, sv[i][2]); t = fmaxf(t, sv[i][3]);
#pragma unroll
            for (int d = 1; d < 16; d <<= 1)
                t = fmaxf(t, __shfl_xor_sync(0xFFFFFFFFu, t, d));
            tmax[i] = t;
            nm[i] = fmaxf(m_run[i], tmax[i]);
            alpha[i] = __expf(m_run[i] - nm[i]);
            float r = 0.f;
#pragma unroll
            for (int j = 0; j < 4; j++) {
                float p = __expf(sv[i][j] - nm[i]);
                sv[i][j] = p;
                r += p;
            }
#pragma unroll
            for (int d = 1; d < 16; d <<= 1)
                r += __shfl_xor_sync(0xFFFFFFFFu, r, d);
            rs[i] = r;
            l_run[i] = l_run[i] * alpha[i] + rs[i];
            m_run[i] = nm[i];
        }
#pragma unroll
        for (int i = 0; i < 4; i++)
#pragma unroll
            for (int j = 0; j < 8; j++) acc[i][j] *= alpha[i];

        __syncthreads();   // all S reads of KsPs done before overwriting with P
        // write P transposed: Ps[s][m]
#pragma unroll
        for (int j = 0; j < 4; j++)
#pragma unroll
            for (int i = 0; i < 4; i++)
                KsPs[(tx*4 + j) * 68 + ty*4 + i] = sv[i][j];
        __syncthreads();

        // ---- O += P V ----
#pragma unroll 4
        for (int s = 0; s < FK; s++) {
            float4 pa = *(const float4*)&KsPs[s * 68 + ty * 4];
            float4 v0 = *(const float4*)&Vs[s * 132 + tx * 8];
            float4 v1 = *(const float4*)&Vs[s * 132 + tx * 8 + 4];
            float pv[4] = {pa.x, pa.y, pa.z, pa.w};
            float vv[8] = {v0.x, v0.y, v0.z, v0.w, v1.x, v1.y, v1.z, v1.w};
#pragma unroll
            for (int i = 0; i < 4; i++)
#pragma unroll
                for (int j = 0; j < 8; j++)
                    acc[i][j] += pv[i] * vv[j];
        }
        __syncthreads();   // before next tile reload
    }

    // ---- epilogue ----
#pragma unroll
    for (int i = 0; i < 4; i++) {
        float inv = 1.0f / l_run[i];
        int m = q0 + ty * 4 + i;
        float* obase = att + ((size_t)(b*TT + m) * NQH + n) * HD + tx * 8;
        float4 o0 = make_float4(acc[i][0]*inv, acc[i][1]*inv, acc[i][2]*inv, acc[i][3]*inv);
        float4 o1 = make_float4(acc[i][4]*inv, acc[i][5]*inv, acc[i][6]*inv, acc[i][7]*inv);
        *(float4*)&obase[0] = o0;
        *(float4*)&obase[4] = o1;
    }
}

// ---------------------------------------------------------------------------
// Launch
// ---------------------------------------------------------------------------
extern "C" void kernel_launch(void* const* d_in, const int* in_sizes, int n_in,
                              void* d_out, int out_size)
{
    const float* x        = (const float*)d_in[0];
    const int*   seg      = (const int*)d_in[1];
    const float* wq       = (const float*)d_in[2];
    const float* wk       = (const float*)d_in[3];
    const float* wv       = (const float*)d_in[4];
    const float* wo       = (const float*)d_in[5];
    const float* q_scale  = (const float*)d_in[6];
    const float* k_scale  = (const float*)d_in[7];
    float* out            = (float*)d_out;

    float* qkv; cudaGetSymbolAddress((void**)&qkv, g_qkv);
    float* att; cudaGetSymbolAddress((void**)&att, g_att);
    int*   pos; cudaGetSymbolAddress((void**)&pos, g_pos);

    static bool attr_set = false;
    (void)attr_set;
    cudaFuncSetAttribute(flash_kernel, cudaFuncAttributeMaxDynamicSharedMemorySize,
                         FLASH_SMEM_BYTES);

    // 1) positions
    pos_kernel<<<TB, 256>>>(seg, pos);

    // 2) QKV projections into g_qkv
    {
        dim3 gq((NQH*HD)/GBN, BT/GBM);
        sgemm_kernel<<<gq, 256>>>(x, TD, wq, NQH*HD, qkv + 0, QKV_LD, BT, NQH*HD, TD);
        dim3 gk((NKH*HD)/GBN, BT/GBM);
        sgemm_kernel<<<gk, 256>>>(x, TD, wk, NKH*HD, qkv + NQH*HD, QKV_LD, BT, NKH*HD, TD);
        sgemm_kernel<<<gk, 256>>>(x, TD, wv, NKH*HD, qkv + NQH*HD + NKH*HD, QKV_LD, BT, NKH*HD, TD);
    }

    // 3) RMSNorm + RoPE (in place on q,k columns)
    {
        dim3 g(BT, NQH + NKH);
        normrope_kernel<<<g, HD>>>(qkv, pos, q_scale, k_scale);
    }

    // 4) flash attention
    {
        dim3 g(TT/FQ, NQH, TB);
        flash_kernel<<<g, 256, FLASH_SMEM_BYTES>>>(qkv, pos, seg, att);
    }

    // 5) output projection
    {
        dim3 g(TD/GBN, BT/GBM);
        sgemm_kernel<<<g, 256>>>(att, NQH*HD, wo, TD, out, TD, BT, TD, NQH*HD);
    }
}

// round 5
// speedup vs baseline: 3.1348x; 3.1348x over previous
#include <cuda_runtime.h>
#include <cuda_bf16.h>
#include <math.h>
#include <stdint.h>

#define TB 2
#define TT 2048
#define TD 1024
#define NQH 16
#define NKH 8
#define HD 128
#define BT (TB*TT)          // 4096
#define QKV_LD 4096
#define ATT_LD 2048
#define EPSV 1e-6f
#define SCALEV 0.08838834764831845f
#define LOG2_THETA 19.9315685693241740f
#define MASKV (-3.0e38f)
#define NEGI (-1e30f)

typedef __nv_bfloat16 bf16;
typedef __nv_bfloat162 bf162;

// Scratch (device globals; no runtime allocation)
__device__ float g_qkv[(size_t)BT*QKV_LD];                    // 64MB fp32 qkv
__device__ bf16 g_xh[(size_t)BT*TD],     g_xl[(size_t)BT*TD];
__device__ bf16 g_wh[(size_t)TD*QKV_LD], g_wl[(size_t)TD*QKV_LD];
__device__ bf16 g_qh[(size_t)BT*QKV_LD], g_ql[(size_t)BT*QKV_LD];
__device__ bf16 g_ah[(size_t)BT*ATT_LD], g_al[(size_t)BT*ATT_LD];
__device__ bf16 g_oh[(size_t)ATT_LD*TD], g_ol[(size_t)ATT_LD*TD];
__device__ int  g_pos[BT];

// ---------------------------------------------------------------------------
// helpers
// ---------------------------------------------------------------------------
__device__ __forceinline__ uint32_t s2u(const void* p){
    return (uint32_t)__cvta_generic_to_shared(p);
}
__device__ __forceinline__ void ldm4(uint32_t* r, uint32_t a){
    asm volatile("ldmatrix.sync.aligned.m8n8.x4.shared.b16 {%0,%1,%2,%3}, [%4];"
        : "=r"(r[0]),"=r"(r[1]),"=r"(r[2]),"=r"(r[3]) : "r"(a));
}
__device__ __forceinline__ void ldm4t(uint32_t* r, uint32_t a){
    asm volatile("ldmatrix.sync.aligned.m8n8.x4.trans.shared.b16 {%0,%1,%2,%3}, [%4];"
        : "=r"(r[0]),"=r"(r[1]),"=r"(r[2]),"=r"(r[3]) : "r"(a));
}
__device__ __forceinline__ void mma16816(float* c, const uint32_t* a, const uint32_t* b){
    asm volatile("mma.sync.aligned.m16n8k16.row.col.f32.bf16.bf16.f32 "
        "{%0,%1,%2,%3}, {%4,%5,%6,%7}, {%8,%9}, {%0,%1,%2,%3};"
        : "+f"(c[0]),"+f"(c[1]),"+f"(c[2]),"+f"(c[3])
        : "r"(a[0]),"r"(a[1]),"r"(a[2]),"r"(a[3]),"r"(b[0]),"r"(b[1]));
}
__device__ __forceinline__ void hl_pack(float x, float y, uint32_t& h, uint32_t& l){
    bf16 hx = __float2bfloat16(x), hy = __float2bfloat16(y);
    bf162 th = __halves2bfloat162(hx, hy);
    h = *reinterpret_cast<uint32_t*>(&th);
    bf162 tl = __floats2bfloat162_rn(x - __bfloat162float(hx), y - __bfloat162float(hy));
    l = *reinterpret_cast<uint32_t*>(&tl);
}

// ---------------------------------------------------------------------------
// Kernel: positions from segment ids
// ---------------------------------------------------------------------------
__global__ void pos_kernel(const int* __restrict__ seg, int* __restrict__ pos) {
    const int b = blockIdx.x;
    const int tid = threadIdx.x;
    __shared__ int red[256];
    int mx = -2147483647 - 1;
    for (int t = tid; t < TT; t += 256) mx = max(mx, seg[b*TT + t]);
    red[tid] = mx; __syncthreads();
    for (int s = 128; s > 0; s >>= 1) {
        if (tid < s) red[tid] = max(red[tid], red[tid + s]);
        __syncthreads();
    }
    const int gmax = red[0];
    __syncthreads();
    int idx = TT;
    for (int t = tid; t < TT; t += 256)
        if (seg[b*TT + t] == gmax && t < idx) idx = t;
    red[tid] = idx; __syncthreads();
    for (int s = 128; s > 0; s >>= 1) {
        if (tid < s) red[tid] = min(red[tid], red[tid + s]);
        __syncthreads();
    }
    const int off = red[0];
    for (int t = tid; t < TT; t += 256) {
        int sv = seg[b*TT + t];
        pos[b*TT + t] = (sv != 0) ? (t - off) : (1 << 30);
    }
}

// ---------------------------------------------------------------------------
// Kernel: fp32 -> bf16 hi/lo split
// ---------------------------------------------------------------------------
__global__ void split_kernel(const float* __restrict__ src, bf16* __restrict__ dh,
                             bf16* __restrict__ dl, int rows, int cols,
                             int sld, int dld, int doff)
{
    const int c4 = cols >> 2;
    const int total = rows * c4;
    for (int i = blockIdx.x*blockDim.x + threadIdx.x; i < total; i += gridDim.x*blockDim.x) {
        int r = i / c4;
        int c = (i - r*c4) * 4;
        float4 v = *(const float4*)&src[(size_t)r*sld + c];
        bf16 h0=__float2bfloat16(v.x), h1=__float2bfloat16(v.y);
        bf16 h2=__float2bfloat16(v.z), h3=__float2bfloat16(v.w);
        bf16 l0=__float2bfloat16(v.x-__bfloat162float(h0));
        bf16 l1=__float2bfloat16(v.y-__bfloat162float(h1));
        bf16 l2=__float2bfloat16(v.z-__bfloat162float(h2));
        bf16 l3=__float2bfloat16(v.w-__bfloat162float(h3));
        size_t o = (size_t)r*dld + doff + c;
        *(bf162*)&dh[o]   = __halves2bfloat162(h0,h1);
        *(bf162*)&dh[o+2] = __halves2bfloat162(h2,h3);
        *(bf162*)&dl[o]   = __halves2bfloat162(l0,l1);
        *(bf162*)&dl[o+2] = __halves2bfloat162(l2,l3);
    }
}

// ---------------------------------------------------------------------------
// Kernel: RMSNorm + RoPE (in-place on fp32 qkv)
// ---------------------------------------------------------------------------
__global__ void normrope_kernel(float* __restrict__ qkv,
                                const int* __restrict__ pos,
                                const float* __restrict__ q_scale,
                                const float* __restrict__ k_scale)
{
    const int bt = blockIdx.x;
    const int head = blockIdx.y;
    const int h = threadIdx.x;
    const bool isq = head < NQH;
    const int colbase = isq ? head * HD : (NQH*HD) + (head - NQH) * HD;
    float* base = qkv + (size_t)bt * QKV_LD + colbase;

    float v = base[h];
    float ss = v * v;
#pragma unroll
    for (int d = 16; d > 0; d >>= 1) ss += __shfl_xor_sync(0xFFFFFFFFu, ss, d);
    __shared__ float wsum[4];
    const int lane = h & 31, wid = h >> 5;
    if (lane == 0) wsum[wid] = ss;
    __syncthreads();
    float total = wsum[0] + wsum[1] + wsum[2] + wsum[3];
    float rms = sqrtf(total * (1.0f / HD) + EPSV);
    const float* sc = isq ? q_scale : k_scale;
    float nv = sc[h] * v / rms;

    __shared__ float buf[HD];
    buf[h] = nv;
    __syncthreads();

    const int p = pos[bt];
    if (h < HD/2) {
        float x1 = buf[h];
        float x2 = buf[h + HD/2];
        float inv_freq = exp2f(-(float)h * (LOG2_THETA / (HD/2)));
        float ang = (float)p * inv_freq;
        float s, c;
        sincosf(ang, &s, &c);
        base[h]        = x1 * c - x2 * s;
        base[h + HD/2] = x2 * c + x1 * s;
    }
}

// ---------------------------------------------------------------------------
// Kernel: bf16x3 GEMM  C_f32[M,N] = Ah@Bh + Ah@Bl + Al@Bh
// A row-major [M][K], B row-major (k-major) [K][N]
// 128x128 block, 8 warps (2m x 4n), warp tile 64x32, K-step 32, double-buffered
// ---------------------------------------------------------------------------
#define GA_STR 40
#define GB_STR 136
#define G_ASZ (128*GA_STR)
#define G_BSZ (32*GB_STR)
#define G_BUF (2*G_ASZ + 2*G_BSZ)
#define GEMM_SMEM (2*G_BUF*2)

__global__ __launch_bounds__(256,1)
void gemm3_kernel(const bf16* __restrict__ Ah, const bf16* __restrict__ Al, int lda,
                  const bf16* __restrict__ Bh, const bf16* __restrict__ Bl, int ldb,
                  float* __restrict__ C, int ldc, int Kd)
{
    extern __shared__ bf16 sm[];
    const int tid = threadIdx.x, lane = tid&31, warp = tid>>5;
    const int wm = warp&1, wn = warp>>1;
    const int m0 = blockIdx.y*128, n0 = blockIdx.x*128;

    float acc[4][4][4];
#pragma unroll
    for (int i=0;i<4;i++)
#pragma unroll
        for (int j=0;j<4;j++)
#pragma unroll
            for (int q=0;q<4;q++) acc[i][j][q]=0.f;

    uint4 ra_h[2], ra_l[2], rb_h[2], rb_l[2];

    auto loadT = [&](int k0){
#pragma unroll
        for (int i=0;i<2;i++){
            int f = tid + i*256;
            int r = f>>2, k8 = (f&3)*8;
            size_t ao = (size_t)(m0+r)*lda + k0 + k8;
            ra_h[i] = *(const uint4*)(Ah+ao);
            ra_l[i] = *(const uint4*)(Al+ao);
            int kr = f>>4, n8 = (f&15)*8;
            size_t bo = (size_t)(k0+kr)*ldb + n0 + n8;
            rb_h[i] = *(const uint4*)(Bh+bo);
            rb_l[i] = *(const uint4*)(Bl+bo);
        }
    };
    auto storeT = [&](int buf){
        bf16* base = sm + buf*G_BUF;
#pragma unroll
        for (int i=0;i<2;i++){
            int f = tid + i*256;
            int r = f>>2, k8 = (f&3)*8;
            *(uint4*)(base + r*GA_STR + k8) = ra_h[i];
            *(uint4*)(base + G_ASZ + r*GA_STR + k8) = ra_l[i];
            int kr = f>>4, n8 = (f&15)*8;
            *(uint4*)(base + 2*G_ASZ + kr*GB_STR + n8) = rb_h[i];
            *(uint4*)(base + 2*G_ASZ + G_BSZ + kr*GB_STR + n8) = rb_l[i];
        }
    };

    const int nk = Kd >> 5;
    loadT(0); storeT(0); __syncthreads();
    int cur = 0;
    const int ar = lane&15, ac8 = (lane>>4)*8;
    for (int t=0; t<nk; t++){
        if (t+1 < nk) loadT((t+1)<<5);
        bf16* base = sm + cur*G_BUF;
        uint32_t ash = s2u(base), asl = s2u(base+G_ASZ);
        uint32_t bsh = s2u(base+2*G_ASZ), bsl = s2u(base+2*G_ASZ+G_BSZ);
#pragma unroll
        for (int ks=0; ks<32; ks+=16){
            uint32_t ah[4][4], al[4][4];
#pragma unroll
            for (int mt=0; mt<4; mt++){
                uint32_t off = (uint32_t)((wm*64 + mt*16 + ar)*GA_STR + ks + ac8)*2;
                ldm4(ah[mt], ash + off);
                ldm4(al[mt], asl + off);
            }
#pragma unroll
            for (int ntp=0; ntp<2; ntp++){
                uint32_t bh[4], bl[4];
                uint32_t off = (uint32_t)((ks + ar)*GB_STR + wn*32 + ntp*16 + ac8)*2;
                ldm4t(bh, bsh + off);
                ldm4t(bl, bsl + off);
#pragma unroll
                for (int mt=0; mt<4; mt++){
#pragma unroll
                    for (int sb=0; sb<2; sb++){
                        float* c = acc[mt][ntp*2+sb];
                        mma16816(c, ah[mt], bh + sb*2);
                        mma16816(c, ah[mt], bl + sb*2);
                        mma16816(c, al[mt], bh + sb*2);
                    }
                }
            }
        }
        if (t+1 < nk) storeT(cur^1);
        __syncthreads();
        cur ^= 1;
    }
#pragma unroll
    for (int mt=0; mt<4; mt++){
        int r = m0 + wm*64 + mt*16 + (lane>>2);
#pragma unroll
        for (int nt=0; nt<4; nt++){
            int cc = n0 + wn*32 + nt*8 + 2*(lane&3);
            *(float2*)&C[(size_t)r*ldc + cc]     = make_float2(acc[mt][nt][0], acc[mt][nt][1]);
            *(float2*)&C[(size_t)(r+8)*ldc + cc] = make_float2(acc[mt][nt][2], acc[mt][nt][3]);
        }
    }
}

// ---------------------------------------------------------------------------
// Kernel: flash attention with bf16x3 mma
// grid (T/64, NQH, B), 128 threads (4 warps, 16 q-rows each); Bq=Bk=64
// ---------------------------------------------------------------------------
#define FSTR 136
#define FLASH_SMEM (6*64*FSTR*2 + 4*64*4)

__global__ __launch_bounds__(128)
void flash3_kernel(const bf16* __restrict__ Gh, const bf16* __restrict__ Gl,
                   const int* __restrict__ pos, const int* __restrict__ seg,
                   bf16* __restrict__ atth, bf16* __restrict__ attl)
{
    extern __shared__ bf16 fsm[];
    bf16* Qh = fsm;           bf16* Ql = Qh + 64*FSTR;
    bf16* Kh = Ql + 64*FSTR;  bf16* Kl = Kh + 64*FSTR;
    bf16* Vh = Kl + 64*FSTR;  bf16* Vl = Vh + 64*FSTR;
    int* posq = (int*)(Vl + 64*FSTR);
    int* segq = posq+64; int* posk = segq+64; int* segk = posk+64;

    const int tid=threadIdx.x, lane=tid&31, warp=tid>>5;
    const int qt=blockIdx.x, n=blockIdx.y, b=blockIdx.z;
    const int kh = n>>1, q0 = qt*64;

#pragma unroll
    for (int i=0;i<8;i++){
        int f = tid + i*128; int r = f>>4; int h8 = (f&15)*8;
        size_t go = (size_t)(b*TT + q0 + r)*QKV_LD + n*HD + h8;
        *(uint4*)(Qh + r*FSTR + h8) = *(const uint4*)(Gh + go);
        *(uint4*)(Ql + r*FSTR + h8) = *(const uint4*)(Gl + go);
    }
    if (tid<64){ posq[tid]=pos[b*TT+q0+tid]; segq[tid]=seg[b*TT+q0+tid]; }
    __syncthreads();

    const int rql = warp*16 + (lane>>2);
    const int pq0=posq[rql], sq0=segq[rql], pq1=posq[rql+8], sq1=segq[rql+8];

    float m0r=NEGI, m1r=NEGI, l0=0.f, l1=0.f;
    float oacc[16][4];
#pragma unroll
    for (int i=0;i<16;i++)
#pragma unroll
        for (int j=0;j<4;j++) oacc[i][j]=0.f;

    uint32_t qh_s = s2u(Qh), ql_s = s2u(Ql), kh_s = s2u(Kh), kl_s = s2u(Kl);
    uint32_t vh_s = s2u(Vh), vl_s = s2u(Vl);

    const int ar = lane&15, ac8 = (lane>>4)*8;              // A + trans-B pattern
    const int br = ((lane>>4)<<3) + (lane&7), bc8 = lane&8; // non-trans-B pattern
    const int cb = 2*(lane&3);

    const int ntk = qt+1;
    for (int kt=0; kt<ntk; kt++){
        const int s0g = kt*64;
#pragma unroll
        for (int i=0;i<8;i++){
            int f = tid + i*128; int r = f>>4; int h8 = (f&15)*8;
            size_t gk = (size_t)(b*TT + s0g + r)*QKV_LD + NQH*HD + kh*HD + h8;
            *(uint4*)(Kh + r*FSTR + h8) = *(const uint4*)(Gh + gk);
            *(uint4*)(Kl + r*FSTR + h8) = *(const uint4*)(Gl + gk);
            size_t gv = gk + NKH*HD;
            *(uint4*)(Vh + r*FSTR + h8) = *(const uint4*)(Gh + gv);
            *(uint4*)(Vl + r*FSTR + h8) = *(const uint4*)(Gl + gv);
        }
        if (tid<64){ posk[tid]=pos[b*TT+s0g+tid]; segk[tid]=seg[b*TT+s0g+tid]; }
        __syncthreads();

        float sacc[8][4];
#pragma unroll
        for (int i=0;i<8;i++)
#pragma unroll
            for (int j=0;j<4;j++) sacc[i][j]=0.f;

        // ---- S = Q K^T ----
#pragma unroll
        for (int ks=0; ks<HD; ks+=16){
            uint32_t ah[4], al[4];
            uint32_t aoff = (uint32_t)((warp*16 + ar)*FSTR + ks + ac8)*2;
            ldm4(ah, qh_s + aoff);
            ldm4(al, ql_s + aoff);
#pragma unroll
            for (int ntp=0; ntp<4; ntp++){
                uint32_t bh[4], bl[4];
                uint32_t boff = (uint32_t)((ntp*16 + br)*FSTR + ks + bc8)*2;
                ldm4(bh, kh_s + boff);
                ldm4(bl, kl_s + boff);
#pragma unroll
                for (int sb=0; sb<2; sb++){
                    float* c = sacc[ntp*2+sb];
                    mma16816(c, ah, bh + sb*2);
                    mma16816(c, ah, bl + sb*2);
                    mma16816(c, al, bh + sb*2);
                }
            }
        }

        // ---- scale + mask + online softmax ----
        float t0=NEGI, t1=NEGI;
#pragma unroll
        for (int nt=0; nt<8; nt++){
            int c0 = nt*8 + cb;
            int pk0=posk[c0], sk0=segk[c0], pk1=posk[c0+1], sk1=segk[c0+1];
            float v00 = (pk0<=pq0 && sk0==sq0) ? sacc[nt][0]*SCALEV : MASKV;
            float v01 = (pk1<=pq0 && sk1==sq0) ? sacc[nt][1]*SCALEV : MASKV;
            float v10 = (pk0<=pq1 && sk0==sq1) ? sacc[nt][2]*SCALEV : MASKV;
            float v11 = (pk1<=pq1 && sk1==sq1) ? sacc[nt][3]*SCALEV : MASKV;
            sacc[nt][0]=v00; sacc[nt][1]=v01; sacc[nt][2]=v10; sacc[nt][3]=v11;
            t0 = fmaxf(t0, fmaxf(v00,v01));
            t1 = fmaxf(t1, fmaxf(v10,v11));
        }
        t0 = fmaxf(t0, __shfl_xor_sync(0xFFFFFFFFu, t0, 1));
        t0 = fmaxf(t0, __shfl_xor_sync(0xFFFFFFFFu, t0, 2));
        t1 = fmaxf(t1, __shfl_xor_sync(0xFFFFFFFFu, t1, 1));
        t1 = fmaxf(t1, __shfl_xor_sync(0xFFFFFFFFu, t1, 2));
        float nm0 = fmaxf(m0r, t0), nm1 = fmaxf(m1r, t1);
        float a0 = __expf(m0r-nm0), a1 = __expf(m1r-nm1);
        float rs0=0.f, rs1=0.f;
#pragma unroll
        for (int nt=0; nt<8; nt++){
            float p00=__expf(sacc[nt][0]-nm0), p01=__expf(sacc[nt][1]-nm0);
            float p10=__expf(sacc[nt][2]-nm1), p11=__expf(sacc[nt][3]-nm1);
            sacc[nt][0]=p00; sacc[nt][1]=p01; sacc[nt][2]=p10; sacc[nt][3]=p11;
            rs0 += p00+p01; rs1 += p10+p11;
        }
        rs0 += __shfl_xor_sync(0xFFFFFFFFu, rs0, 1);
        rs0 += __shfl_xor_sync(0xFFFFFFFFu, rs0, 2);
        rs1 += __shfl_xor_sync(0xFFFFFFFFu, rs1, 1);
        rs1 += __shfl_xor_sync(0xFFFFFFFFu, rs1, 2);
        l0 = l0*a0 + rs0; l1 = l1*a1 + rs1;
        m0r = nm0; m1r = nm1;
#pragma unroll
        for (int nt=0; nt<16; nt++){
            oacc[nt][0]*=a0; oacc[nt][1]*=a0; oacc[nt][2]*=a1; oacc[nt][3]*=a1;
        }

        // ---- O += P V ----
#pragma unroll
        for (int ks=0; ks<4; ks++){
            uint32_t pah[4], pal[4];
            hl_pack(sacc[2*ks][0],   sacc[2*ks][1],   pah[0], pal[0]);
            hl_pack(sacc[2*ks][2],   sacc[2*ks][3],   pah[1], pal[1]);
            hl_pack(sacc[2*ks+1][0], sacc[2*ks+1][1], pah[2], pal[2]);
            hl_pack(sacc[2*ks+1][2], sacc[2*ks+1][3], pah[3], pal[3]);
#pragma unroll
            for (int ntp=0; ntp<8; ntp++){
                uint32_t bh[4], bl[4];
                uint32_t off = (uint32_t)((ks*16 + ar)*FSTR + ntp*16 + ac8)*2;
                ldm4t(bh, vh_s + off);
                ldm4t(bl, vl_s + off);
#pragma unroll
                for (int sb=0; sb<2; sb++){
                    float* c = oacc[ntp*2+sb];
                    mma16816(c, pah, bh + sb*2);
                    mma16816(c, pah, bl + sb*2);
                    mma16816(c, pal, bh + sb*2);
                }
            }
        }
        __syncthreads();
    }

    // ---- epilogue: write hi/lo bf16 attention output ----
    float il0 = 1.f/l0, il1 = 1.f/l1;
#pragma unroll
    for (int nt=0; nt<16; nt++){
        int hcol = nt*8 + cb;
        size_t o0 = (size_t)(b*TT + q0 + warp*16 + (lane>>2))*ATT_LD + n*HD + hcol;
        uint32_t h, l;
        hl_pack(oacc[nt][0]*il0, oacc[nt][1]*il0, h, l);
        *(uint32_t*)(atth + o0) = h; *(uint32_t*)(attl + o0) = l;
        hl_pack(oacc[nt][2]*il1, oacc[nt][3]*il1, h, l);
        *(uint32_t*)(atth + o0 + 8*ATT_LD) = h; *(uint32_t*)(attl + o0 + 8*ATT_LD) = l;
    }
}

// ---------------------------------------------------------------------------
// Launch
// ---------------------------------------------------------------------------
extern "C" void kernel_launch(void* const* d_in, const int* in_sizes, int n_in,
                              void* d_out, int out_size)
{
    const float* x       = (const float*)d_in[0];
    const int*   seg     = (const int*)d_in[1];
    const float* wq      = (const float*)d_in[2];
    const float* wk      = (const float*)d_in[3];
    const float* wv      = (const float*)d_in[4];
    const float* wo      = (const float*)d_in[5];
    const float* q_scale = (const float*)d_in[6];
    const float* k_scale = (const float*)d_in[7];
    float* out           = (float*)d_out;

    float* qkv; cudaGetSymbolAddress((void**)&qkv, g_qkv);
    bf16 *xh, *xl, *wh, *wl, *qh, *ql, *ah, *al, *oh, *ol;
    cudaGetSymbolAddress((void**)&xh, g_xh); cudaGetSymbolAddress((void**)&xl, g_xl);
    cudaGetSymbolAddress((void**)&wh, g_wh); cudaGetSymbolAddress((void**)&wl, g_wl);
    cudaGetSymbolAddress((void**)&qh, g_qh); cudaGetSymbolAddress((void**)&ql, g_ql);
    cudaGetSymbolAddress((void**)&ah, g_ah); cudaGetSymbolAddress((void**)&al, g_al);
    cudaGetSymbolAddress((void**)&oh, g_oh); cudaGetSymbolAddress((void**)&ol, g_ol);
    int* pos; cudaGetSymbolAddress((void**)&pos, g_pos);

    cudaFuncSetAttribute(gemm3_kernel, cudaFuncAttributeMaxDynamicSharedMemorySize, GEMM_SMEM);
    cudaFuncSetAttribute(flash3_kernel, cudaFuncAttributeMaxDynamicSharedMemorySize, FLASH_SMEM);

    // 1) positions
    pos_kernel<<<TB, 256>>>(seg, pos);

    // 2) split inputs / weights to bf16 hi/lo
    split_kernel<<<2048, 256>>>(x,  xh, xl, BT, TD, TD, TD, 0);
    split_kernel<<<1024, 256>>>(wq, wh, wl, TD, NQH*HD, NQH*HD, QKV_LD, 0);
    split_kernel<<<512,  256>>>(wk, wh, wl, TD, NKH*HD, NKH*HD, QKV_LD, NQH*HD);
    split_kernel<<<512,  256>>>(wv, wh, wl, TD, NKH*HD, NKH*HD, QKV_LD, NQH*HD + NKH*HD);
    split_kernel<<<1024, 256>>>(wo, oh, ol, ATT_LD, TD, TD, TD, 0);

    // 3) QKV projection (bf16x3 tensor-core GEMM)
    {
        dim3 g(QKV_LD/128, BT/128);
        gemm3_kernel<<<g, 256, GEMM_SMEM>>>(xh, xl, TD, wh, wl, QKV_LD, qkv, QKV_LD, TD);
    }

    // 4) RMSNorm + RoPE (fp32, in place)
    {
        dim3 g(BT, NQH + NKH);
        normrope_kernel<<<g, HD>>>(qkv, pos, q_scale, k_scale);
    }

    // 5) split qkv to bf16 hi/lo
    split_kernel<<<4096, 256>>>(qkv, qh, ql, BT, QKV_LD, QKV_LD, QKV_LD, 0);

    // 6) flash attention (bf16x3 mma) -> split bf16 att output
    {
        dim3 g(TT/64, NQH, TB);
        flash3_kernel<<<g, 128, FLASH_SMEM>>>(qh, ql, pos, seg, ah, al);
    }

    // 7) output projection
    {
        dim3 g(TD/128, BT/128);
        gemm3_kernel<<<g, 256, GEMM_SMEM>>>(ah, al, ATT_LD, oh, ol, TD, out, TD, ATT_LD);
    }
}